// round 5
// baseline (speedup 1.0000x reference)
#include <cuda_runtime.h>
#include <cuda_bf16.h>
#include <cstdint>

// ---------------- problem constants ----------------
constexpr int B_ROWS = 8192;
constexpr int N_ROWS = 8192;
constexpr int D_DIM  = 768;

constexpr int BM = 128, BN = 128, BK = 32;
constexpr int NK = D_DIM / BK;      // 24
constexpr int STG = 4;              // cp.async stages
constexpr int THREADS = 256;        // 8 warps: 2 (M) x 4 (N), warp tile 64x32
constexpr int ROWB = 80;            // padded smem row bytes (32 bf16 = 64B data + 16B pad)
constexpr int TILE = BM * ROWB;     // 10240 B per operand per stage
// smem: A stages [0, STG*TILE), B stages [STG*TILE, 2*STG*TILE). Epilogue reuses it.
constexpr int SMEM_MAIN = 2 * STG * TILE;          // 81920
constexpr int EPI_STRIDE = 132;                    // floats per row (pad 128 -> 132)
constexpr int SMEM_EPI  = BM * EPI_STRIDE * 4;     // 67584
constexpr int SMEM_TOTAL = SMEM_MAIN > SMEM_EPI ? SMEM_MAIN : SMEM_EPI;

// ---------------- scratch (__device__ globals: allocation-free) ----------------
__device__ __align__(128) unsigned char g_xb[(size_t)B_ROWS * D_DIM * 2]; // bf16 row-major
__device__ __align__(128) unsigned char g_yb[(size_t)N_ROWS * D_DIM * 2];
__device__ float g_x2[B_ROWS];
__device__ float g_y2[N_ROWS];

// ---------------- PTX helpers (base ISA only — no tcgen05) ----------------
__device__ __forceinline__ uint32_t smem_u32(const void* p) {
    uint32_t a;
    asm("{ .reg .u64 t; cvta.to.shared.u64 t, %1; cvt.u32.u64 %0, t; }"
        : "=r"(a) : "l"(p));
    return a;
}

#define CP16(dst, src) \
    asm volatile("cp.async.cg.shared.global [%0], [%1], 16;" :: "r"(dst), "l"(src))
#define CPCOMMIT() asm volatile("cp.async.commit_group;")
#define CPWAIT(n)  asm volatile("cp.async.wait_group %0;" :: "n"(n))

#define LDSM4(r, a)                                                            \
    asm volatile("ldmatrix.sync.aligned.m8n8.x4.shared.b16 {%0,%1,%2,%3}, [%4];" \
                 : "=r"((r)[0]), "=r"((r)[1]), "=r"((r)[2]), "=r"((r)[3])      \
                 : "r"(a))

__device__ __forceinline__ void mma16816(float* c, const uint32_t* a, const uint32_t* b) {
    asm volatile(
        "mma.sync.aligned.m16n8k16.row.col.f32.bf16.bf16.f32 "
        "{%0,%1,%2,%3}, {%4,%5,%6,%7}, {%8,%9}, {%0,%1,%2,%3};"
        : "+f"(c[0]), "+f"(c[1]), "+f"(c[2]), "+f"(c[3])
        : "r"(a[0]), "r"(a[1]), "r"(a[2]), "r"(a[3]), "r"(b[0]), "r"(b[1]));
}

// ---------------- kernel 1: fp32 -> bf16 row-major + row norms ----------------
__global__ void __launch_bounds__(128) prep_kernel(const float* __restrict__ x,
                                                   const float* __restrict__ y) {
    const int wid = threadIdx.x >> 5, lid = threadIdx.x & 31;
    const int row = blockIdx.x * 4 + wid;  // 0..16383: x rows then y rows

    const float4* src;
    uint2* dst;
    float* nrm;
    int r;
    if (row < B_ROWS) {
        r = row;
        src = reinterpret_cast<const float4*>(x + (size_t)r * D_DIM);
        dst = reinterpret_cast<uint2*>(g_xb + (size_t)r * D_DIM * 2);
        nrm = g_x2;
    } else {
        r = row - B_ROWS;
        src = reinterpret_cast<const float4*>(y + (size_t)r * D_DIM);
        dst = reinterpret_cast<uint2*>(g_yb + (size_t)r * D_DIM * 2);
        nrm = g_y2;
    }

    float ss = 0.f;
#pragma unroll
    for (int j = 0; j < D_DIM / 128; j++) {  // 6 float4 per lane
        const int idx = j * 32 + lid;
        const float4 v = src[idx];
        ss = fmaf(v.x, v.x, ss);
        ss = fmaf(v.y, v.y, ss);
        ss = fmaf(v.z, v.z, ss);
        ss = fmaf(v.w, v.w, ss);
        __nv_bfloat162 h0 = __floats2bfloat162_rn(v.x, v.y);
        __nv_bfloat162 h1 = __floats2bfloat162_rn(v.z, v.w);
        uint2 o;
        o.x = *reinterpret_cast<uint32_t*>(&h0);
        o.y = *reinterpret_cast<uint32_t*>(&h1);
        dst[idx] = o;
    }
#pragma unroll
    for (int o = 16; o; o >>= 1) ss += __shfl_xor_sync(0xffffffffu, ss, o);
    if (lid == 0) nrm[r] = ss;
}

// ---------------- kernel 2: bf16 mma.sync GEMM + distance epilogue ----------------
extern __shared__ unsigned char smem[];

__global__ void __launch_bounds__(THREADS) gemm_kernel(float* __restrict__ out) {
    const uint32_t sb = smem_u32(smem);
    const int tid = threadIdx.x;
    const int lid = tid & 31;
    const int wid = tid >> 5;
    const int warpM = wid & 1;   // 0..1
    const int warpN = wid >> 1;  // 0..3
    const int bm = blockIdx.y, bn = blockIdx.x;

    // ---- per-thread cp.async descriptors (2 A chunks + 2 B chunks per stage) ----
    const int c0 = tid, c1 = tid + THREADS;
    const int r0 = c0 >> 2, s0 = c0 & 3;
    const int r1 = c1 >> 2, s1 = c1 & 3;
    const char* gA0 = (const char*)g_xb + ((size_t)(bm * BM + r0) * D_DIM) * 2 + s0 * 16;
    const char* gA1 = (const char*)g_xb + ((size_t)(bm * BM + r1) * D_DIM) * 2 + s1 * 16;
    const char* gB0 = (const char*)g_yb + ((size_t)(bn * BN + r0) * D_DIM) * 2 + s0 * 16;
    const char* gB1 = (const char*)g_yb + ((size_t)(bn * BN + r1) * D_DIM) * 2 + s1 * 16;
    const uint32_t dA0 = sb + r0 * ROWB + s0 * 16;
    const uint32_t dA1 = sb + r1 * ROWB + s1 * 16;
    const uint32_t dB0 = sb + STG * TILE + r0 * ROWB + s0 * 16;
    const uint32_t dB1 = sb + STG * TILE + r1 * ROWB + s1 * 16;

    auto load_stage = [&](int st, int kt) {
        const uint32_t so = (uint32_t)st * TILE;
        const size_t go = (size_t)kt * (BK * 2);
        CP16(dA0 + so, gA0 + go);
        CP16(dA1 + so, gA1 + go);
        CP16(dB0 + so, gB0 + go);
        CP16(dB1 + so, gB1 + go);
    };

    // ---- ldmatrix per-thread offsets ----
    // A: 4 m16 tiles; lanes 0-15 -> rows 0-15, lanes 16-31 -> same rows @ +16B
    uint32_t aoff[4], boff[2];
#pragma unroll
    for (int t = 0; t < 4; t++)
        aoff[t] = (uint32_t)(warpM * 64 + t * 16 + (lid & 15)) * ROWB + (lid >> 4) * 16;
    // B: 2 n16 groups; lanes0-7 n0-7@0, 8-15 n0-7@16, 16-23 n8-15@0, 24-31 n8-15@16
#pragma unroll
    for (int g = 0; g < 2; g++)
        boff[g] = (uint32_t)(warpN * 32 + g * 16 + (lid & 7) + ((lid >> 4) << 3)) * ROWB +
                  ((lid >> 3) & 1) * 16;

    uint32_t fa[2][4][4], fb[2][2][4];
    auto lds_frags = [&](int st, int s16, uint32_t (*pfa)[4], uint32_t (*pfb)[4]) {
        const uint32_t ab = sb + (uint32_t)st * TILE + s16 * 32;
        const uint32_t bb = sb + STG * TILE + (uint32_t)st * TILE + s16 * 32;
#pragma unroll
        for (int t = 0; t < 4; t++) LDSM4(pfa[t], ab + aoff[t]);
#pragma unroll
        for (int g = 0; g < 2; g++) LDSM4(pfb[g], bb + boff[g]);
    };

    float acc[4][4][4];
#pragma unroll
    for (int i = 0; i < 4; i++)
#pragma unroll
        for (int j = 0; j < 4; j++)
#pragma unroll
            for (int k = 0; k < 4; k++) acc[i][j][k] = 0.f;

    auto mma_all = [&](uint32_t (*pfa)[4], uint32_t (*pfb)[4]) {
#pragma unroll
        for (int tm = 0; tm < 4; tm++)
#pragma unroll
            for (int tn = 0; tn < 4; tn++)
                mma16816(acc[tm][tn], pfa[tm], &pfb[tn >> 1][(tn & 1) * 2]);
    };

    // ---- prologue ----
#pragma unroll
    for (int s = 0; s < STG - 1; s++) {
        load_stage(s, s);
        CPCOMMIT();
    }
    CPWAIT(STG - 2);
    __syncthreads();
    lds_frags(0, 0, fa[0], fb[0]);

    // ---- mainloop ----
    for (int i = 0; i < NK; i++) {
        const int st_i = i % STG;
        lds_frags(st_i, 1, fa[1], fb[1]);
        mma_all(fa[0], fb[0]);

        const int nx = i + STG - 1;
        if (nx < NK) load_stage(nx % STG, nx);
        CPCOMMIT();
        CPWAIT(STG - 2);
        __syncthreads();

        if (i + 1 < NK) lds_frags((i + 1) % STG, 0, fa[0], fb[0]);
        mma_all(fa[1], fb[1]);
    }

    // ---- epilogue: d = x2 + y2 - 2*acc, clamp, transpose-stage, coalesced store ----
    float x2v[4][2], y2v[4][2];
#pragma unroll
    for (int t = 0; t < 4; t++) {
        const int m = bm * BM + warpM * 64 + t * 16 + (lid >> 2);
        x2v[t][0] = __ldg(&g_x2[m]);
        x2v[t][1] = __ldg(&g_x2[m + 8]);
        const int n = bn * BN + warpN * 32 + t * 8 + 2 * (lid & 3);
        y2v[t][0] = __ldg(&g_y2[n]);
        y2v[t][1] = __ldg(&g_y2[n + 1]);
    }

    __syncthreads();  // mainloop smem reads done everywhere before reuse
    float* st = (float*)smem;
#pragma unroll
    for (int tm = 0; tm < 4; tm++) {
#pragma unroll
        for (int tn = 0; tn < 4; tn++) {
            const float* c = acc[tm][tn];
            const int m0 = warpM * 64 + tm * 16 + (lid >> 2);
            const int n0 = warpN * 32 + tn * 8 + 2 * (lid & 3);
            float2 lo, hi;
            lo.x = fmaxf(fmaf(-2.f, c[0], x2v[tm][0] + y2v[tn][0]), 0.f);
            lo.y = fmaxf(fmaf(-2.f, c[1], x2v[tm][0] + y2v[tn][1]), 0.f);
            hi.x = fmaxf(fmaf(-2.f, c[2], x2v[tm][1] + y2v[tn][0]), 0.f);
            hi.y = fmaxf(fmaf(-2.f, c[3], x2v[tm][1] + y2v[tn][1]), 0.f);
            *reinterpret_cast<float2*>(&st[m0 * EPI_STRIDE + n0]) = lo;
            *reinterpret_cast<float2*>(&st[(m0 + 8) * EPI_STRIDE + n0]) = hi;
        }
    }
    __syncthreads();

    const int row = tid >> 1, half = tid & 1;
    const float4* sp = reinterpret_cast<const float4*>(st + row * EPI_STRIDE + half * 64);
    float4* op = reinterpret_cast<float4*>(out + (size_t)(bm * BM + row) * N_ROWS +
                                           bn * BN + half * 64);
#pragma unroll
    for (int j = 0; j < 16; j++) op[j] = sp[j];
}

// ---------------- launch ----------------
extern "C" void kernel_launch(void* const* d_in, const int* in_sizes, int n_in,
                              void* d_out, int out_size) {
    (void)in_sizes; (void)n_in; (void)out_size;
    const float* x = (const float*)d_in[0];
    const float* y = (const float*)d_in[1];
    float* out = (float*)d_out;

    cudaFuncSetAttribute(gemm_kernel, cudaFuncAttributeMaxDynamicSharedMemorySize,
                         (int)SMEM_TOTAL);

    prep_kernel<<<(B_ROWS + N_ROWS) / 4, 128>>>(x, y);

    dim3 grid(N_ROWS / BN, B_ROWS / BM);
    gemm_kernel<<<grid, THREADS, SMEM_TOTAL>>>(out);
}

// round 7
// speedup vs baseline: 1.1226x; 1.1226x over previous
#include <cuda_runtime.h>
#include <cuda_bf16.h>
#include <cstdint>

// ---------------- problem constants ----------------
constexpr int B_ROWS = 8192;
constexpr int N_ROWS = 8192;
constexpr int D_DIM  = 768;

constexpr int BM = 128, BN = 128, BK = 64;
constexpr int NK = D_DIM / BK;      // 12
constexpr int STG = 3;              // cp.async stages
constexpr int THREADS = 256;        // 8 warps: 2 (M) x 4 (N), warp tile 64x32
constexpr int ROWB = 144;           // padded smem row bytes (64 bf16 = 128B + 16B pad)
constexpr int TILE = BM * ROWB;     // 18432 B per operand per stage
constexpr int SMEM_MAIN = 2 * STG * TILE;          // 110592
constexpr int EPI_STRIDE = 132;                    // floats per row
constexpr int SMEM_EPI  = BM * EPI_STRIDE * 4;     // 67584 (reuses mainloop smem)
constexpr int SMEM_TOTAL = SMEM_MAIN;

// ---------------- scratch (__device__ globals: allocation-free) ----------------
__device__ __align__(128) unsigned char g_xb[(size_t)B_ROWS * D_DIM * 2]; // bf16 row-major
__device__ __align__(128) unsigned char g_yb[(size_t)N_ROWS * D_DIM * 2];
__device__ float g_x2[B_ROWS];
__device__ float g_y2[N_ROWS];

// ---------------- PTX helpers (base ISA only) ----------------
__device__ __forceinline__ uint32_t smem_u32(const void* p) {
    uint32_t a;
    asm("{ .reg .u64 t; cvta.to.shared.u64 t, %1; cvt.u32.u64 %0, t; }"
        : "=r"(a) : "l"(p));
    return a;
}

#define CP16(dst, src) \
    asm volatile("cp.async.cg.shared.global [%0], [%1], 16;" :: "r"(dst), "l"(src))
#define CPCOMMIT() asm volatile("cp.async.commit_group;")
#define CPWAIT(n)  asm volatile("cp.async.wait_group %0;" :: "n"(n))

#define LDSM4(r, a)                                                            \
    asm volatile("ldmatrix.sync.aligned.m8n8.x4.shared.b16 {%0,%1,%2,%3}, [%4];" \
                 : "=r"((r)[0]), "=r"((r)[1]), "=r"((r)[2]), "=r"((r)[3])      \
                 : "r"(a))

__device__ __forceinline__ void mma16816(float* c, const uint32_t* a, const uint32_t* b) {
    asm volatile(
        "mma.sync.aligned.m16n8k16.row.col.f32.bf16.bf16.f32 "
        "{%0,%1,%2,%3}, {%4,%5,%6,%7}, {%8,%9}, {%0,%1,%2,%3};"
        : "+f"(c[0]), "+f"(c[1]), "+f"(c[2]), "+f"(c[3])
        : "r"(a[0]), "r"(a[1]), "r"(a[2]), "r"(a[3]), "r"(b[0]), "r"(b[1]));
}

// ---------------- kernel 1: fp32 -> bf16 row-major + row norms ----------------
__global__ void __launch_bounds__(128) prep_kernel(const float* __restrict__ x,
                                                   const float* __restrict__ y) {
    const int wid = threadIdx.x >> 5, lid = threadIdx.x & 31;
    const int row = blockIdx.x * 4 + wid;  // 0..16383: x rows then y rows

    const float4* src;
    uint2* dst;
    float* nrm;
    int r;
    if (row < B_ROWS) {
        r = row;
        src = reinterpret_cast<const float4*>(x + (size_t)r * D_DIM);
        dst = reinterpret_cast<uint2*>(g_xb + (size_t)r * D_DIM * 2);
        nrm = g_x2;
    } else {
        r = row - B_ROWS;
        src = reinterpret_cast<const float4*>(y + (size_t)r * D_DIM);
        dst = reinterpret_cast<uint2*>(g_yb + (size_t)r * D_DIM * 2);
        nrm = g_y2;
    }

    float ss = 0.f;
#pragma unroll
    for (int j = 0; j < D_DIM / 128; j++) {  // 6 float4 per lane
        const int idx = j * 32 + lid;
        const float4 v = src[idx];
        ss = fmaf(v.x, v.x, ss);
        ss = fmaf(v.y, v.y, ss);
        ss = fmaf(v.z, v.z, ss);
        ss = fmaf(v.w, v.w, ss);
        __nv_bfloat162 h0 = __floats2bfloat162_rn(v.x, v.y);
        __nv_bfloat162 h1 = __floats2bfloat162_rn(v.z, v.w);
        uint2 o;
        o.x = *reinterpret_cast<uint32_t*>(&h0);
        o.y = *reinterpret_cast<uint32_t*>(&h1);
        dst[idx] = o;
    }
#pragma unroll
    for (int o = 16; o; o >>= 1) ss += __shfl_xor_sync(0xffffffffu, ss, o);
    if (lid == 0) nrm[r] = ss;
}

// ---------------- kernel 2: bf16 mma.sync GEMM + distance epilogue ----------------
extern __shared__ unsigned char smem[];

__global__ void __launch_bounds__(THREADS, 2) gemm_kernel(float* __restrict__ out) {
    const uint32_t sb = smem_u32(smem);
    const int tid = threadIdx.x;
    const int lid = tid & 31;
    const int wid = tid >> 5;
    const int warpM = wid & 1;   // 0..1
    const int warpN = wid >> 1;  // 0..3
    const int bm = blockIdx.y, bn = blockIdx.x;

    // ---- cp.async: 4 x 16B chunks per thread per operand per stage ----
    // stage row = 128B data in ROWB=144B padded rows
    uint32_t dA[4], dB[4];
    const char* gA[4];
    const char* gB[4];
#pragma unroll
    for (int t = 0; t < 4; t++) {
        const int c = tid + t * THREADS;     // 0..1023
        const int r = c >> 3, sc = c & 7;    // row 0..127, 16B-chunk 0..7
        gA[t] = (const char*)g_xb + ((size_t)(bm * BM + r) * D_DIM) * 2 + sc * 16;
        gB[t] = (const char*)g_yb + ((size_t)(bn * BN + r) * D_DIM) * 2 + sc * 16;
        dA[t] = sb + r * ROWB + sc * 16;
        dB[t] = sb + STG * TILE + r * ROWB + sc * 16;
    }

    auto load_stage = [&](int st, int kt) {
        const uint32_t so = (uint32_t)st * TILE;
        const size_t go = (size_t)kt * (BK * 2);
#pragma unroll
        for (int t = 0; t < 4; t++) CP16(dA[t] + so, gA[t] + go);
#pragma unroll
        for (int t = 0; t < 4; t++) CP16(dB[t] + so, gB[t] + go);
    };

    // ---- ldmatrix per-thread offsets (within a stage, k16 step adds s*32B) ----
    uint32_t aoff[4], boff[2];
#pragma unroll
    for (int t = 0; t < 4; t++)
        aoff[t] = (uint32_t)(warpM * 64 + t * 16 + (lid & 15)) * ROWB + (lid >> 4) * 16;
#pragma unroll
    for (int g = 0; g < 2; g++)
        boff[g] = (uint32_t)(warpN * 32 + g * 16 + (lid & 7) + ((lid >> 4) << 3)) * ROWB +
                  ((lid >> 3) & 1) * 16;

    float acc[4][4][4];
#pragma unroll
    for (int i = 0; i < 4; i++)
#pragma unroll
        for (int j = 0; j < 4; j++)
#pragma unroll
            for (int k = 0; k < 4; k++) acc[i][j][k] = 0.f;

    // ---- prologue: stages 0,1 ----
#pragma unroll
    for (int s = 0; s < STG - 1; s++) {
        load_stage(s, s);
        CPCOMMIT();
    }

    // ---- mainloop: 12 iterations, one barrier each ----
    for (int i = 0; i < NK; i++) {
        CPWAIT(STG - 2);        // k-tile i resident
        __syncthreads();        // everyone done reading stage (i-1)%STG

        const int nx = i + STG - 1;
        if (nx < NK) load_stage(nx % STG, nx);
        CPCOMMIT();

        const int st = i % STG;
        const uint32_t ab = sb + (uint32_t)st * TILE;
        const uint32_t bb = ab + STG * TILE;
#pragma unroll
        for (int s = 0; s < BK / 16; s++) {   // 4 k16 steps
            uint32_t fa[4][4], fb[2][4];
#pragma unroll
            for (int t = 0; t < 4; t++) LDSM4(fa[t], ab + aoff[t] + s * 32);
#pragma unroll
            for (int g = 0; g < 2; g++) LDSM4(fb[g], bb + boff[g] + s * 32);
#pragma unroll
            for (int tm = 0; tm < 4; tm++)
#pragma unroll
                for (int tn = 0; tn < 4; tn++)
                    mma16816(acc[tm][tn], fa[tm], &fb[tn >> 1][(tn & 1) * 2]);
        }
    }

    // ---- epilogue: d = x2 + y2 - 2*acc, clamp, transpose-stage, coalesced store ----
    float x2v[4][2], y2v[4][2];
#pragma unroll
    for (int t = 0; t < 4; t++) {
        const int m = bm * BM + warpM * 64 + t * 16 + (lid >> 2);
        x2v[t][0] = __ldg(&g_x2[m]);
        x2v[t][1] = __ldg(&g_x2[m + 8]);
        const int n = bn * BN + warpN * 32 + t * 8 + 2 * (lid & 3);
        y2v[t][0] = __ldg(&g_y2[n]);
        y2v[t][1] = __ldg(&g_y2[n + 1]);
    }

    __syncthreads();  // mainloop smem reads done everywhere before reuse
    float* st = (float*)smem;
#pragma unroll
    for (int tm = 0; tm < 4; tm++) {
#pragma unroll
        for (int tn = 0; tn < 4; tn++) {
            const float* c = acc[tm][tn];
            const int m0 = warpM * 64 + tm * 16 + (lid >> 2);
            const int n0 = warpN * 32 + tn * 8 + 2 * (lid & 3);
            float2 lo, hi;
            lo.x = fmaxf(fmaf(-2.f, c[0], x2v[tm][0] + y2v[tn][0]), 0.f);
            lo.y = fmaxf(fmaf(-2.f, c[1], x2v[tm][0] + y2v[tn][1]), 0.f);
            hi.x = fmaxf(fmaf(-2.f, c[2], x2v[tm][1] + y2v[tn][0]), 0.f);
            hi.y = fmaxf(fmaf(-2.f, c[3], x2v[tm][1] + y2v[tn][1]), 0.f);
            *reinterpret_cast<float2*>(&st[m0 * EPI_STRIDE + n0]) = lo;
            *reinterpret_cast<float2*>(&st[(m0 + 8) * EPI_STRIDE + n0]) = hi;
        }
    }
    __syncthreads();

    const int row = tid >> 1, half = tid & 1;
    const float4* sp = reinterpret_cast<const float4*>(st + row * EPI_STRIDE + half * 64);
    float4* op = reinterpret_cast<float4*>(out + (size_t)(bm * BM + row) * N_ROWS +
                                           bn * BN + half * 64);
#pragma unroll
    for (int j = 0; j < 16; j++) op[j] = sp[j];
}

// ---------------- launch ----------------
extern "C" void kernel_launch(void* const* d_in, const int* in_sizes, int n_in,
                              void* d_out, int out_size) {
    (void)in_sizes; (void)n_in; (void)out_size;
    const float* x = (const float*)d_in[0];
    const float* y = (const float*)d_in[1];
    float* out = (float*)d_out;

    cudaFuncSetAttribute(gemm_kernel, cudaFuncAttributeMaxDynamicSharedMemorySize,
                         (int)SMEM_TOTAL);

    prep_kernel<<<(B_ROWS + N_ROWS) / 4, 128>>>(x, y);

    dim3 grid(N_ROWS / BN, B_ROWS / BM);
    gemm_kernel<<<grid, THREADS, SMEM_TOTAL>>>(out);
}

// round 8
// speedup vs baseline: 1.1262x; 1.0032x over previous
#include <cuda_runtime.h>
#include <cuda_bf16.h>
#include <cstdint>

// ---------------- problem constants ----------------
constexpr int B_ROWS = 8192;
constexpr int N_ROWS = 8192;
constexpr int D_DIM  = 768;

constexpr int BM = 128, BN = 128, BK = 64;
constexpr int NK = D_DIM / BK;      // 12
constexpr int STG = 3;              // cp.async stages
constexpr int THREADS = 256;        // 8 warps: 2 (M) x 4 (N), warp tile 64x32
constexpr int ROWB = 144;           // padded smem row bytes (64 bf16 = 128B + 16B pad)
constexpr int TILE = BM * ROWB;     // 18432 B per operand per stage
constexpr int SMEM_MAIN = 2 * STG * TILE;          // 110592
constexpr int EPI_STRIDE = 132;                    // floats per row
constexpr int SMEM_EPI  = BM * EPI_STRIDE * 4;     // 67584 (reuses mainloop smem)
constexpr int SMEM_TOTAL = SMEM_MAIN;

// ---------------- scratch (__device__ globals: allocation-free) ----------------
__device__ __align__(128) unsigned char g_xb[(size_t)B_ROWS * D_DIM * 2]; // bf16 row-major
__device__ __align__(128) unsigned char g_yb[(size_t)N_ROWS * D_DIM * 2];
__device__ float g_x2[B_ROWS];
__device__ float g_y2[N_ROWS];

// ---------------- PTX helpers (base ISA only) ----------------
__device__ __forceinline__ uint32_t smem_u32(const void* p) {
    uint32_t a;
    asm("{ .reg .u64 t; cvta.to.shared.u64 t, %1; cvt.u32.u64 %0, t; }"
        : "=r"(a) : "l"(p));
    return a;
}

#define CP16(dst, src) \
    asm volatile("cp.async.cg.shared.global [%0], [%1], 16;" :: "r"(dst), "l"(src))
#define CPCOMMIT() asm volatile("cp.async.commit_group;")
#define CPWAIT(n)  asm volatile("cp.async.wait_group %0;" :: "n"(n))

#define LDSM4(r, a)                                                            \
    asm volatile("ldmatrix.sync.aligned.m8n8.x4.shared.b16 {%0,%1,%2,%3}, [%4];" \
                 : "=r"((r)[0]), "=r"((r)[1]), "=r"((r)[2]), "=r"((r)[3])      \
                 : "r"(a))

__device__ __forceinline__ void mma16816(float* c, const uint32_t* a, const uint32_t* b) {
    asm volatile(
        "mma.sync.aligned.m16n8k16.row.col.f32.bf16.bf16.f32 "
        "{%0,%1,%2,%3}, {%4,%5,%6,%7}, {%8,%9}, {%0,%1,%2,%3};"
        : "+f"(c[0]), "+f"(c[1]), "+f"(c[2]), "+f"(c[3])
        : "r"(a[0]), "r"(a[1]), "r"(a[2]), "r"(a[3]), "r"(b[0]), "r"(b[1]));
}

// ---------------- kernel 1: fp32 -> bf16 row-major + row norms ----------------
__global__ void __launch_bounds__(128) prep_kernel(const float* __restrict__ x,
                                                   const float* __restrict__ y) {
    const int wid = threadIdx.x >> 5, lid = threadIdx.x & 31;
    const int row = blockIdx.x * 4 + wid;  // 0..16383: x rows then y rows

    const float4* src;
    uint2* dst;
    float* nrm;
    int r;
    if (row < B_ROWS) {
        r = row;
        src = reinterpret_cast<const float4*>(x + (size_t)r * D_DIM);
        dst = reinterpret_cast<uint2*>(g_xb + (size_t)r * D_DIM * 2);
        nrm = g_x2;
    } else {
        r = row - B_ROWS;
        src = reinterpret_cast<const float4*>(y + (size_t)r * D_DIM);
        dst = reinterpret_cast<uint2*>(g_yb + (size_t)r * D_DIM * 2);
        nrm = g_y2;
    }

    float ss = 0.f;
#pragma unroll
    for (int j = 0; j < D_DIM / 128; j++) {  // 6 float4 per lane
        const int idx = j * 32 + lid;
        const float4 v = src[idx];
        ss = fmaf(v.x, v.x, ss);
        ss = fmaf(v.y, v.y, ss);
        ss = fmaf(v.z, v.z, ss);
        ss = fmaf(v.w, v.w, ss);
        __nv_bfloat162 h0 = __floats2bfloat162_rn(v.x, v.y);
        __nv_bfloat162 h1 = __floats2bfloat162_rn(v.z, v.w);
        uint2 o;
        o.x = *reinterpret_cast<uint32_t*>(&h0);
        o.y = *reinterpret_cast<uint32_t*>(&h1);
        dst[idx] = o;
    }
#pragma unroll
    for (int o = 16; o; o >>= 1) ss += __shfl_xor_sync(0xffffffffu, ss, o);
    if (lid == 0) nrm[r] = ss;
}

// ---------------- kernel 2: bf16 mma.sync GEMM + distance epilogue ----------------
extern __shared__ unsigned char smem[];

__global__ void __launch_bounds__(THREADS, 2) gemm_kernel(float* __restrict__ out) {
    const uint32_t sb = smem_u32(smem);
    const int tid = threadIdx.x;
    const int lid = tid & 31;
    const int wid = tid >> 5;
    const int warpM = wid & 1;   // 0..1
    const int warpN = wid >> 1;  // 0..3
    const int bm = blockIdx.y, bn = blockIdx.x;

    // ---- cp.async: 4 x 16B chunks per thread per operand per stage ----
    // stage row = 128B data in ROWB=144B padded rows
    uint32_t dA[4], dB[4];
    const char* gA[4];
    const char* gB[4];
#pragma unroll
    for (int t = 0; t < 4; t++) {
        const int c = tid + t * THREADS;     // 0..1023
        const int r = c >> 3, sc = c & 7;    // row 0..127, 16B-chunk 0..7
        gA[t] = (const char*)g_xb + ((size_t)(bm * BM + r) * D_DIM) * 2 + sc * 16;
        gB[t] = (const char*)g_yb + ((size_t)(bn * BN + r) * D_DIM) * 2 + sc * 16;
        dA[t] = sb + r * ROWB + sc * 16;
        dB[t] = sb + STG * TILE + r * ROWB + sc * 16;
    }

    auto load_stage = [&](int st, int kt) {
        const uint32_t so = (uint32_t)st * TILE;
        const size_t go = (size_t)kt * (BK * 2);
#pragma unroll
        for (int t = 0; t < 4; t++) CP16(dA[t] + so, gA[t] + go);
#pragma unroll
        for (int t = 0; t < 4; t++) CP16(dB[t] + so, gB[t] + go);
    };

    // ---- ldmatrix per-thread offsets (within a stage, k16 step adds s*32B) ----
    uint32_t aoff[4], boff[2];
#pragma unroll
    for (int t = 0; t < 4; t++)
        aoff[t] = (uint32_t)(warpM * 64 + t * 16 + (lid & 15)) * ROWB + (lid >> 4) * 16;
#pragma unroll
    for (int g = 0; g < 2; g++)
        boff[g] = (uint32_t)(warpN * 32 + g * 16 + (lid & 7) + ((lid >> 4) << 3)) * ROWB +
                  ((lid >> 3) & 1) * 16;

    float acc[4][4][4];
#pragma unroll
    for (int i = 0; i < 4; i++)
#pragma unroll
        for (int j = 0; j < 4; j++)
#pragma unroll
            for (int k = 0; k < 4; k++) acc[i][j][k] = 0.f;

    // ---- prologue: stages 0,1 ----
#pragma unroll
    for (int s = 0; s < STG - 1; s++) {
        load_stage(s, s);
        CPCOMMIT();
    }

    // ---- mainloop: 12 iterations, one barrier each ----
    for (int i = 0; i < NK; i++) {
        CPWAIT(STG - 2);        // k-tile i resident
        __syncthreads();        // everyone done reading stage (i-1)%STG

        const int nx = i + STG - 1;
        if (nx < NK) load_stage(nx % STG, nx);
        CPCOMMIT();

        const int st = i % STG;
        const uint32_t ab = sb + (uint32_t)st * TILE;
        const uint32_t bb = ab + STG * TILE;
#pragma unroll
        for (int s = 0; s < BK / 16; s++) {   // 4 k16 steps
            uint32_t fa[4][4], fb[2][4];
#pragma unroll
            for (int t = 0; t < 4; t++) LDSM4(fa[t], ab + aoff[t] + s * 32);
#pragma unroll
            for (int g = 0; g < 2; g++) LDSM4(fb[g], bb + boff[g] + s * 32);
#pragma unroll
            for (int tm = 0; tm < 4; tm++)
#pragma unroll
                for (int tn = 0; tn < 4; tn++)
                    mma16816(acc[tm][tn], fa[tm], &fb[tn >> 1][(tn & 1) * 2]);
        }
    }

    // ---- epilogue: d = x2 + y2 - 2*acc, clamp, transpose-stage, coalesced store ----
    float x2v[4][2], y2v[4][2];
#pragma unroll
    for (int t = 0; t < 4; t++) {
        const int m = bm * BM + warpM * 64 + t * 16 + (lid >> 2);
        x2v[t][0] = __ldg(&g_x2[m]);
        x2v[t][1] = __ldg(&g_x2[m + 8]);
        const int n = bn * BN + warpN * 32 + t * 8 + 2 * (lid & 3);
        y2v[t][0] = __ldg(&g_y2[n]);
        y2v[t][1] = __ldg(&g_y2[n + 1]);
    }

    __syncthreads();  // mainloop smem reads done everywhere before reuse
    float* st = (float*)smem;
#pragma unroll
    for (int tm = 0; tm < 4; tm++) {
#pragma unroll
        for (int tn = 0; tn < 4; tn++) {
            const float* c = acc[tm][tn];
            const int m0 = warpM * 64 + tm * 16 + (lid >> 2);
            const int n0 = warpN * 32 + tn * 8 + 2 * (lid & 3);
            float2 lo, hi;
            lo.x = fmaxf(fmaf(-2.f, c[0], x2v[tm][0] + y2v[tn][0]), 0.f);
            lo.y = fmaxf(fmaf(-2.f, c[1], x2v[tm][0] + y2v[tn][1]), 0.f);
            hi.x = fmaxf(fmaf(-2.f, c[2], x2v[tm][1] + y2v[tn][0]), 0.f);
            hi.y = fmaxf(fmaf(-2.f, c[3], x2v[tm][1] + y2v[tn][1]), 0.f);
            *reinterpret_cast<float2*>(&st[m0 * EPI_STRIDE + n0]) = lo;
            *reinterpret_cast<float2*>(&st[(m0 + 8) * EPI_STRIDE + n0]) = hi;
        }
    }
    __syncthreads();

    const int row = tid >> 1, half = tid & 1;
    const float4* sp = reinterpret_cast<const float4*>(st + row * EPI_STRIDE + half * 64);
    float4* op = reinterpret_cast<float4*>(out + (size_t)(bm * BM + row) * N_ROWS +
                                           bn * BN + half * 64);
#pragma unroll
    for (int j = 0; j < 16; j++) op[j] = sp[j];
}

// ---------------- launch ----------------
extern "C" void kernel_launch(void* const* d_in, const int* in_sizes, int n_in,
                              void* d_out, int out_size) {
    (void)in_sizes; (void)n_in; (void)out_size;
    const float* x = (const float*)d_in[0];
    const float* y = (const float*)d_in[1];
    float* out = (float*)d_out;

    cudaFuncSetAttribute(gemm_kernel, cudaFuncAttributeMaxDynamicSharedMemorySize,
                         (int)SMEM_TOTAL);

    prep_kernel<<<(B_ROWS + N_ROWS) / 4, 128>>>(x, y);

    dim3 grid(N_ROWS / BN, B_ROWS / BM);
    gemm_kernel<<<grid, THREADS, SMEM_TOTAL>>>(out);
}

// round 13
// speedup vs baseline: 1.3635x; 1.2106x over previous
#include <cuda_runtime.h>
#include <cuda_bf16.h>
#include <cstdint>

// ---------------- problem constants ----------------
constexpr int B_ROWS = 8192;
constexpr int N_ROWS = 8192;
constexpr int D_DIM  = 768;

constexpr int BM = 128, BN = 128, BK = 64;
constexpr int NK = D_DIM / BK;      // 12
constexpr int STG = 3;              // cp.async stages
constexpr int THREADS = 128;        // 4 warps: 2 (M) x 2 (N), warp tile 64x64
constexpr int ROWB = 144;           // padded smem row bytes (64 bf16 = 128B + 16B pad)
constexpr int TILE = BM * ROWB;     // 18432 B per operand per stage
constexpr int SMEM_MAIN = 2 * STG * TILE;          // 110592 (x2 CTAs = 221KB/SM)
constexpr int EPI_STRIDE = 132;                    // floats per row
constexpr int SMEM_TOTAL = SMEM_MAIN;

// ---------------- scratch (__device__ globals: allocation-free) ----------------
__device__ __align__(128) unsigned char g_xb[(size_t)B_ROWS * D_DIM * 2]; // bf16 row-major
__device__ __align__(128) unsigned char g_yb[(size_t)N_ROWS * D_DIM * 2];
__device__ float g_x2[B_ROWS];
__device__ float g_y2[N_ROWS];

// ---------------- PTX helpers (base ISA only) ----------------
__device__ __forceinline__ uint32_t smem_u32(const void* p) {
    uint32_t a;
    asm("{ .reg .u64 t; cvta.to.shared.u64 t, %1; cvt.u32.u64 %0, t; }"
        : "=r"(a) : "l"(p));
    return a;
}

#define CP16(dst, src) \
    asm volatile("cp.async.cg.shared.global [%0], [%1], 16;" :: "r"(dst), "l"(src))
#define CPCOMMIT() asm volatile("cp.async.commit_group;")
#define CPWAIT(n)  asm volatile("cp.async.wait_group %0;" :: "n"(n))

#define LDSM4(r, a)                                                            \
    asm volatile("ldmatrix.sync.aligned.m8n8.x4.shared.b16 {%0,%1,%2,%3}, [%4];" \
                 : "=r"((r)[0]), "=r"((r)[1]), "=r"((r)[2]), "=r"((r)[3])      \
                 : "r"(a))

__device__ __forceinline__ void mma16816(float* c, const uint32_t* a, const uint32_t* b) {
    asm volatile(
        "mma.sync.aligned.m16n8k16.row.col.f32.bf16.bf16.f32 "
        "{%0,%1,%2,%3}, {%4,%5,%6,%7}, {%8,%9}, {%0,%1,%2,%3};"
        : "+f"(c[0]), "+f"(c[1]), "+f"(c[2]), "+f"(c[3])
        : "r"(a[0]), "r"(a[1]), "r"(a[2]), "r"(a[3]), "r"(b[0]), "r"(b[1]));
}

// ---------------- kernel 1: fp32 -> bf16 row-major + row norms ----------------
__global__ void __launch_bounds__(128) prep_kernel(const float* __restrict__ x,
                                                   const float* __restrict__ y) {
    const int wid = threadIdx.x >> 5, lid = threadIdx.x & 31;
    const int row = blockIdx.x * 4 + wid;  // 0..16383: x rows then y rows

    const float4* src;
    uint2* dst;
    float* nrm;
    int r;
    if (row < B_ROWS) {
        r = row;
        src = reinterpret_cast<const float4*>(x + (size_t)r * D_DIM);
        dst = reinterpret_cast<uint2*>(g_xb + (size_t)r * D_DIM * 2);
        nrm = g_x2;
    } else {
        r = row - B_ROWS;
        src = reinterpret_cast<const float4*>(y + (size_t)r * D_DIM);
        dst = reinterpret_cast<uint2*>(g_yb + (size_t)r * D_DIM * 2);
        nrm = g_y2;
    }

    float ss = 0.f;
#pragma unroll
    for (int j = 0; j < D_DIM / 128; j++) {  // 6 float4 per lane
        const int idx = j * 32 + lid;
        const float4 v = src[idx];
        ss = fmaf(v.x, v.x, ss);
        ss = fmaf(v.y, v.y, ss);
        ss = fmaf(v.z, v.z, ss);
        ss = fmaf(v.w, v.w, ss);
        __nv_bfloat162 h0 = __floats2bfloat162_rn(v.x, v.y);
        __nv_bfloat162 h1 = __floats2bfloat162_rn(v.z, v.w);
        uint2 o;
        o.x = *reinterpret_cast<uint32_t*>(&h0);
        o.y = *reinterpret_cast<uint32_t*>(&h1);
        dst[idx] = o;
    }
#pragma unroll
    for (int o = 16; o; o >>= 1) ss += __shfl_xor_sync(0xffffffffu, ss, o);
    if (lid == 0) nrm[r] = ss;
}

// ---------------- kernel 2: bf16 mma.sync GEMM + distance epilogue ----------------
extern __shared__ unsigned char smem[];

__global__ void __launch_bounds__(THREADS, 2) gemm_kernel(float* __restrict__ out) {
    const uint32_t sb = smem_u32(smem);
    const int tid = threadIdx.x;
    const int lid = tid & 31;
    const int wid = tid >> 5;
    const int warpM = wid & 1;   // 0..1
    const int warpN = wid >> 1;  // 0..1
    const int bm = blockIdx.y, bn = blockIdx.x;

    // ---- cp.async: 8 x 16B chunks per thread per operand per stage ----
    uint32_t dA[8], dB[8];
    const char* gA[8];
    const char* gB[8];
#pragma unroll
    for (int t = 0; t < 8; t++) {
        const int c = tid + t * THREADS;     // 0..1023
        const int r = c >> 3, sc = c & 7;    // row 0..127, 16B-chunk 0..7
        gA[t] = (const char*)g_xb + ((size_t)(bm * BM + r) * D_DIM) * 2 + sc * 16;
        gB[t] = (const char*)g_yb + ((size_t)(bn * BN + r) * D_DIM) * 2 + sc * 16;
        dA[t] = sb + r * ROWB + sc * 16;
        dB[t] = sb + STG * TILE + r * ROWB + sc * 16;
    }

    auto load_stage = [&](int st, int kt) {
        const uint32_t so = (uint32_t)st * TILE;
        const size_t go = (size_t)kt * (BK * 2);
#pragma unroll
        for (int t = 0; t < 8; t++) CP16(dA[t] + so, gA[t] + go);
#pragma unroll
        for (int t = 0; t < 8; t++) CP16(dB[t] + so, gB[t] + go);
    };

    // ---- ldmatrix per-thread offsets (within a stage, k16 step adds s*32B) ----
    uint32_t aoff[4], boff[4];
#pragma unroll
    for (int t = 0; t < 4; t++)
        aoff[t] = (uint32_t)(warpM * 64 + t * 16 + (lid & 15)) * ROWB + (lid >> 4) * 16;
#pragma unroll
    for (int g = 0; g < 4; g++)
        boff[g] = (uint32_t)(warpN * 64 + g * 16 + (lid & 7) + ((lid >> 4) << 3)) * ROWB +
                  ((lid >> 3) & 1) * 16;

    float acc[4][8][4];
#pragma unroll
    for (int i = 0; i < 4; i++)
#pragma unroll
        for (int j = 0; j < 8; j++)
#pragma unroll
            for (int k = 0; k < 4; k++) acc[i][j][k] = 0.f;

    // ---- prologue: stages 0,1 ----
#pragma unroll
    for (int s = 0; s < STG - 1; s++) {
        load_stage(s, s);
        CPCOMMIT();
    }

    // ---- mainloop: 12 iterations, one barrier each ----
    for (int i = 0; i < NK; i++) {
        CPWAIT(STG - 2);        // k-tile i resident
        __syncthreads();        // everyone done reading stage (i-1)%STG

        const int nx = i + STG - 1;
        if (nx < NK) load_stage(nx % STG, nx);
        CPCOMMIT();

        const int st = i % STG;
        const uint32_t ab = sb + (uint32_t)st * TILE;
        const uint32_t bb = ab + STG * TILE;
#pragma unroll
        for (int s = 0; s < BK / 16; s++) {   // 4 k16 steps
            uint32_t fa[4][4], fb[4][4];
#pragma unroll
            for (int t = 0; t < 4; t++) LDSM4(fa[t], ab + aoff[t] + s * 32);
#pragma unroll
            for (int g = 0; g < 4; g++) LDSM4(fb[g], bb + boff[g] + s * 32);
#pragma unroll
            for (int tm = 0; tm < 4; tm++)
#pragma unroll
                for (int tn = 0; tn < 8; tn++)
                    mma16816(acc[tm][tn], fa[tm], &fb[tn >> 1][(tn & 1) * 2]);
        }
    }

    // ---- epilogue: d = x2 + y2 - 2*acc, clamp, transpose-stage, coalesced store ----
    float x2v[4][2], y2v[8][2];
#pragma unroll
    for (int t = 0; t < 4; t++) {
        const int m = bm * BM + warpM * 64 + t * 16 + (lid >> 2);
        x2v[t][0] = __ldg(&g_x2[m]);
        x2v[t][1] = __ldg(&g_x2[m + 8]);
    }
#pragma unroll
    for (int t = 0; t < 8; t++) {
        const int n = bn * BN + warpN * 64 + t * 8 + 2 * (lid & 3);
        y2v[t][0] = __ldg(&g_y2[n]);
        y2v[t][1] = __ldg(&g_y2[n + 1]);
    }

    __syncthreads();  // mainloop smem reads done everywhere before reuse
    float* st = (float*)smem;
#pragma unroll
    for (int tm = 0; tm < 4; tm++) {
#pragma unroll
        for (int tn = 0; tn < 8; tn++) {
            const float* c = acc[tm][tn];
            const int m0 = warpM * 64 + tm * 16 + (lid >> 2);
            const int n0 = warpN * 64 + tn * 8 + 2 * (lid & 3);
            float2 lo, hi;
            lo.x = fmaxf(fmaf(-2.f, c[0], x2v[tm][0] + y2v[tn][0]), 0.f);
            lo.y = fmaxf(fmaf(-2.f, c[1], x2v[tm][0] + y2v[tn][1]), 0.f);
            hi.x = fmaxf(fmaf(-2.f, c[2], x2v[tm][1] + y2v[tn][0]), 0.f);
            hi.y = fmaxf(fmaf(-2.f, c[3], x2v[tm][1] + y2v[tn][1]), 0.f);
            *reinterpret_cast<float2*>(&st[m0 * EPI_STRIDE + n0]) = lo;
            *reinterpret_cast<float2*>(&st[(m0 + 8) * EPI_STRIDE + n0]) = hi;
        }
    }
    __syncthreads();

    // 128 rows x 128 floats, 128 threads: 32 float4 each, coalesced
#pragma unroll
    for (int k = 0; k < 32; k++) {
        const int id = k * THREADS + tid;
        const int rr = id >> 5, c4 = id & 31;
        const float4 v = *reinterpret_cast<const float4*>(&st[rr * EPI_STRIDE + c4 * 4]);
        *reinterpret_cast<float4*>(out + (size_t)(bm * BM + rr) * N_ROWS + bn * BN + c4 * 4) = v;
    }
}

// ---------------- launch ----------------
extern "C" void kernel_launch(void* const* d_in, const int* in_sizes, int n_in,
                              void* d_out, int out_size) {
    (void)in_sizes; (void)n_in; (void)out_size;
    const float* x = (const float*)d_in[0];
    const float* y = (const float*)d_in[1];
    float* out = (float*)d_out;

    cudaFuncSetAttribute(gemm_kernel, cudaFuncAttributeMaxDynamicSharedMemorySize,
                         (int)SMEM_TOTAL);

    prep_kernel<<<(B_ROWS + N_ROWS) / 4, 128>>>(x, y);

    dim3 grid(N_ROWS / BN, B_ROWS / BM);
    gemm_kernel<<<grid, THREADS, SMEM_TOTAL>>>(out);
}

// round 15
// speedup vs baseline: 1.5299x; 1.1221x over previous
#include <cuda_runtime.h>
#include <cuda_bf16.h>
#include <cstdint>

// ---------------- problem constants ----------------
constexpr int B_ROWS = 8192;
constexpr int N_ROWS = 8192;
constexpr int D_DIM  = 768;

constexpr int BM = 128, BN = 128, BK = 64;
constexpr int NK = D_DIM / BK;      // 12
constexpr int STG = 3;              // cp.async stages
constexpr int THREADS = 128;        // 4 warps: 2 (M) x 2 (N), warp tile 64x64
constexpr int ROWB = 144;           // padded smem row bytes (64 bf16 = 128B + 16B pad)
constexpr int TILE = BM * ROWB;     // 18432 B per operand per stage
constexpr int SMEM_MAIN = 2 * STG * TILE;          // 110592 (x2 CTAs = 221KB/SM)
constexpr int EPI_STRIDE = 132;                    // floats per row
constexpr int SMEM_TOTAL = SMEM_MAIN;
constexpr int GROW = D_DIM * 2;     // global row bytes (1536)

// ---------------- scratch (__device__ globals: allocation-free) ----------------
__device__ __align__(128) unsigned char g_xb[(size_t)B_ROWS * D_DIM * 2]; // bf16 row-major
__device__ __align__(128) unsigned char g_yb[(size_t)N_ROWS * D_DIM * 2];
__device__ float g_x2[B_ROWS];
__device__ float g_y2[N_ROWS];

// ---------------- PTX helpers (base ISA only) ----------------
__device__ __forceinline__ uint32_t smem_u32(const void* p) {
    uint32_t a;
    asm("{ .reg .u64 t; cvta.to.shared.u64 t, %1; cvt.u32.u64 %0, t; }"
        : "=r"(a) : "l"(p));
    return a;
}

#define CP16(dst, src) \
    asm volatile("cp.async.cg.shared.global [%0], [%1], 16;" :: "r"(dst), "l"(src))
#define CPCOMMIT() asm volatile("cp.async.commit_group;")
#define CPWAIT(n)  asm volatile("cp.async.wait_group %0;" :: "n"(n))

#define LDSM4(r, a)                                                            \
    asm volatile("ldmatrix.sync.aligned.m8n8.x4.shared.b16 {%0,%1,%2,%3}, [%4];" \
                 : "=r"((r)[0]), "=r"((r)[1]), "=r"((r)[2]), "=r"((r)[3])      \
                 : "r"(a))

__device__ __forceinline__ void mma16816(float* c, const uint32_t* a, const uint32_t* b) {
    asm volatile(
        "mma.sync.aligned.m16n8k16.row.col.f32.bf16.bf16.f32 "
        "{%0,%1,%2,%3}, {%4,%5,%6,%7}, {%8,%9}, {%0,%1,%2,%3};"
        : "+f"(c[0]), "+f"(c[1]), "+f"(c[2]), "+f"(c[3])
        : "r"(a[0]), "r"(a[1]), "r"(a[2]), "r"(a[3]), "r"(b[0]), "r"(b[1]));
}

// ---------------- kernel 1: fp32 -> bf16 row-major + row norms ----------------
__global__ void __launch_bounds__(128) prep_kernel(const float* __restrict__ x,
                                                   const float* __restrict__ y) {
    const int wid = threadIdx.x >> 5, lid = threadIdx.x & 31;
    const int row = blockIdx.x * 4 + wid;  // 0..16383: x rows then y rows

    const float4* src;
    uint2* dst;
    float* nrm;
    int r;
    if (row < B_ROWS) {
        r = row;
        src = reinterpret_cast<const float4*>(x + (size_t)r * D_DIM);
        dst = reinterpret_cast<uint2*>(g_xb + (size_t)r * D_DIM * 2);
        nrm = g_x2;
    } else {
        r = row - B_ROWS;
        src = reinterpret_cast<const float4*>(y + (size_t)r * D_DIM);
        dst = reinterpret_cast<uint2*>(g_yb + (size_t)r * D_DIM * 2);
        nrm = g_y2;
    }

    float ss = 0.f;
#pragma unroll
    for (int j = 0; j < D_DIM / 128; j++) {  // 6 float4 per lane
        const int idx = j * 32 + lid;
        const float4 v = src[idx];
        ss = fmaf(v.x, v.x, ss);
        ss = fmaf(v.y, v.y, ss);
        ss = fmaf(v.z, v.z, ss);
        ss = fmaf(v.w, v.w, ss);
        __nv_bfloat162 h0 = __floats2bfloat162_rn(v.x, v.y);
        __nv_bfloat162 h1 = __floats2bfloat162_rn(v.z, v.w);
        uint2 o;
        o.x = *reinterpret_cast<uint32_t*>(&h0);
        o.y = *reinterpret_cast<uint32_t*>(&h1);
        dst[idx] = o;
    }
#pragma unroll
    for (int o = 16; o; o >>= 1) ss += __shfl_xor_sync(0xffffffffu, ss, o);
    if (lid == 0) nrm[r] = ss;
}

// ---------------- kernel 2: bf16 mma.sync GEMM + distance epilogue ----------------
extern __shared__ unsigned char smem[];

__global__ void __launch_bounds__(THREADS, 2) gemm_kernel(float* __restrict__ out) {
    const uint32_t sb = smem_u32(smem);
    const int tid = threadIdx.x;
    const int lid = tid & 31;
    const int wid = tid >> 5;
    const int warpM = wid & 1;   // 0..1
    const int warpN = wid >> 1;  // 0..1
    const int bm = blockIdx.y, bn = blockIdx.x;

    // ---- cp.async: base + constant offsets (chunk t = +16 rows) ----
    const int crow = tid >> 3, csc = tid & 7;
    const char* gAb = (const char*)g_xb + (size_t)(bm * BM + crow) * GROW + csc * 16;
    const char* gBb = (const char*)g_yb + (size_t)(bn * BN + crow) * GROW + csc * 16;
    const uint32_t dAb = sb + crow * ROWB + csc * 16;
    const uint32_t dBb = dAb + STG * TILE;

    auto load_stage = [&](int st, int kt) {
        const uint32_t so = (uint32_t)st * TILE;
        const size_t go = (size_t)kt * (BK * 2);
#pragma unroll
        for (int t = 0; t < 8; t++)
            CP16(dAb + so + t * (16 * ROWB), gAb + go + t * (size_t)(16 * GROW));
#pragma unroll
        for (int t = 0; t < 8; t++)
            CP16(dBb + so + t * (16 * ROWB), gBb + go + t * (size_t)(16 * GROW));
    };

    // ---- ldmatrix per-thread offsets (k16 step adds s*32B) ----
    uint32_t aoff[4], boff[4];
#pragma unroll
    for (int t = 0; t < 4; t++)
        aoff[t] = (uint32_t)(warpM * 64 + t * 16 + (lid & 15)) * ROWB + (lid >> 4) * 16;
#pragma unroll
    for (int g = 0; g < 4; g++)
        boff[g] = (uint32_t)(warpN * 64 + g * 16 + (lid & 7) + ((lid >> 4) << 3)) * ROWB +
                  ((lid >> 3) & 1) * 16;

    uint32_t fa[2][4][4], fb[2][4][4];
    auto ldfrags = [&](uint32_t ab, uint32_t bb, int s, int buf) {
#pragma unroll
        for (int t = 0; t < 4; t++) LDSM4(fa[buf][t], ab + aoff[t] + s * 32);
#pragma unroll
        for (int g = 0; g < 4; g++) LDSM4(fb[buf][g], bb + boff[g] + s * 32);
    };

    float acc[4][8][4];
#pragma unroll
    for (int i = 0; i < 4; i++)
#pragma unroll
        for (int j = 0; j < 8; j++)
#pragma unroll
            for (int k = 0; k < 4; k++) acc[i][j][k] = 0.f;

    auto mma_all = [&](int buf) {
#pragma unroll
        for (int tm = 0; tm < 4; tm++)
#pragma unroll
            for (int tn = 0; tn < 8; tn++)
                mma16816(acc[tm][tn], fa[buf][tm], &fb[buf][tn >> 1][(tn & 1) * 2]);
    };

    // ---- prologue: stages 0,1 in flight; frags(stage0, step0) resident ----
#pragma unroll
    for (int s = 0; s < STG - 1; s++) {
        load_stage(s, s);
        CPCOMMIT();
    }
    CPWAIT(STG - 2);
    __syncthreads();
    ldfrags(sb, sb + STG * TILE, 0, 0);

    // ---- mainloop: frag double-buffer, one barrier per BK=64 ----
    for (int i = 0; i < NK; i++) {
        const int st = i % STG;
        const uint32_t ab = sb + (uint32_t)st * TILE;
        const uint32_t bb = ab + STG * TILE;

        ldfrags(ab, bb, 1, 1);
        mma_all(0);

        const int nx = i + STG - 1;
        if (nx < NK) load_stage(nx % STG, nx);
        CPCOMMIT();

        ldfrags(ab, bb, 2, 0);
        mma_all(1);
        ldfrags(ab, bb, 3, 1);
        mma_all(0);

        if (i + 1 < NK) {
            CPWAIT(STG - 2);
            __syncthreads();
            const uint32_t ab2 = sb + (uint32_t)((i + 1) % STG) * TILE;
            ldfrags(ab2, ab2 + STG * TILE, 0, 0);  // overlaps with last MMA pack
        }
        mma_all(1);
    }

    // ---- epilogue: d = x2 + y2 - 2*acc, clamp, transpose-stage, coalesced store ----
    float x2v[4][2], y2v[8][2];
#pragma unroll
    for (int t = 0; t < 4; t++) {
        const int m = bm * BM + warpM * 64 + t * 16 + (lid >> 2);
        x2v[t][0] = __ldg(&g_x2[m]);
        x2v[t][1] = __ldg(&g_x2[m + 8]);
    }
#pragma unroll
    for (int t = 0; t < 8; t++) {
        const int n = bn * BN + warpN * 64 + t * 8 + 2 * (lid & 3);
        y2v[t][0] = __ldg(&g_y2[n]);
        y2v[t][1] = __ldg(&g_y2[n + 1]);
    }

    __syncthreads();  // mainloop smem reads done everywhere before reuse
    float* st = (float*)smem;
#pragma unroll
    for (int tm = 0; tm < 4; tm++) {
#pragma unroll
        for (int tn = 0; tn < 8; tn++) {
            const float* c = acc[tm][tn];
            const int m0 = warpM * 64 + tm * 16 + (lid >> 2);
            const int n0 = warpN * 64 + tn * 8 + 2 * (lid & 3);
            float2 lo, hi;
            lo.x = fmaxf(fmaf(-2.f, c[0], x2v[tm][0] + y2v[tn][0]), 0.f);
            lo.y = fmaxf(fmaf(-2.f, c[1], x2v[tm][0] + y2v[tn][1]), 0.f);
            hi.x = fmaxf(fmaf(-2.f, c[2], x2v[tm][1] + y2v[tn][0]), 0.f);
            hi.y = fmaxf(fmaf(-2.f, c[3], x2v[tm][1] + y2v[tn][1]), 0.f);
            *reinterpret_cast<float2*>(&st[m0 * EPI_STRIDE + n0]) = lo;
            *reinterpret_cast<float2*>(&st[(m0 + 8) * EPI_STRIDE + n0]) = hi;
        }
    }
    __syncthreads();

    // 128 rows x 128 floats, 128 threads: 32 float4 each, coalesced
#pragma unroll
    for (int k = 0; k < 32; k++) {
        const int id = k * THREADS + tid;
        const int rr = id >> 5, c4 = id & 31;
        const float4 v = *reinterpret_cast<const float4*>(&st[rr * EPI_STRIDE + c4 * 4]);
        *reinterpret_cast<float4*>(out + (size_t)(bm * BM + rr) * N_ROWS + bn * BN + c4 * 4) = v;
    }
}

// ---------------- launch ----------------
extern "C" void kernel_launch(void* const* d_in, const int* in_sizes, int n_in,
                              void* d_out, int out_size) {
    (void)in_sizes; (void)n_in; (void)out_size;
    const float* x = (const float*)d_in[0];
    const float* y = (const float*)d_in[1];
    float* out = (float*)d_out;

    cudaFuncSetAttribute(gemm_kernel, cudaFuncAttributeMaxDynamicSharedMemorySize,
                         (int)SMEM_TOTAL);

    prep_kernel<<<(B_ROWS + N_ROWS) / 4, 128>>>(x, y);

    dim3 grid(N_ROWS / BN, B_ROWS / BM);
    gemm_kernel<<<grid, THREADS, SMEM_TOTAL>>>(out);
}

// round 17
// speedup vs baseline: 1.6251x; 1.0622x over previous
#include <cuda_runtime.h>
#include <cuda_bf16.h>
#include <cstdint>

// ---------------- problem constants ----------------
constexpr int B_ROWS = 8192;
constexpr int N_ROWS = 8192;
constexpr int D_DIM  = 768;

constexpr int BM = 128, BN = 128, BK = 64;
constexpr int NK = D_DIM / BK;      // 12 (divisible by STG -> stage rotation continuous)
constexpr int STG = 3;              // cp.async stages
constexpr int THREADS = 128;        // 4 warps: 2 (M) x 2 (N), warp tile 64x64
constexpr int ROWB = 144;           // padded smem row bytes (64 bf16 = 128B + 16B pad)
constexpr int TILE = BM * ROWB;     // 18432 B per operand per stage
constexpr int SMEM_TOTAL = 2 * STG * TILE;  // 110592 (x2 CTAs = 221KB/SM)
constexpr int GROW = D_DIM * 2;     // global row bytes (1536)
constexpr int NTILES = (B_ROWS / BM) * (N_ROWS / BN);  // 4096
constexpr int NBN = N_ROWS / BN;    // 64

// ---------------- scratch (__device__ globals: allocation-free) ----------------
__device__ __align__(128) unsigned char g_xb[(size_t)B_ROWS * D_DIM * 2]; // bf16 row-major
__device__ __align__(128) unsigned char g_yb[(size_t)N_ROWS * D_DIM * 2];
__device__ float g_x2[B_ROWS];
__device__ float g_y2[N_ROWS];

// ---------------- PTX helpers (base ISA only) ----------------
__device__ __forceinline__ uint32_t smem_u32(const void* p) {
    uint32_t a;
    asm("{ .reg .u64 t; cvta.to.shared.u64 t, %1; cvt.u32.u64 %0, t; }"
        : "=r"(a) : "l"(p));
    return a;
}

#define CP16(dst, src) \
    asm volatile("cp.async.cg.shared.global [%0], [%1], 16;" :: "r"(dst), "l"(src))
#define CPCOMMIT() asm volatile("cp.async.commit_group;")
#define CPWAIT(n)  asm volatile("cp.async.wait_group %0;" :: "n"(n))

#define LDSM4(r, a)                                                            \
    asm volatile("ldmatrix.sync.aligned.m8n8.x4.shared.b16 {%0,%1,%2,%3}, [%4];" \
                 : "=r"((r)[0]), "=r"((r)[1]), "=r"((r)[2]), "=r"((r)[3])      \
                 : "r"(a))

__device__ __forceinline__ void mma16816(float* c, const uint32_t* a, const uint32_t* b) {
    asm volatile(
        "mma.sync.aligned.m16n8k16.row.col.f32.bf16.bf16.f32 "
        "{%0,%1,%2,%3}, {%4,%5,%6,%7}, {%8,%9}, {%0,%1,%2,%3};"
        : "+f"(c[0]), "+f"(c[1]), "+f"(c[2]), "+f"(c[3])
        : "r"(a[0]), "r"(a[1]), "r"(a[2]), "r"(a[3]), "r"(b[0]), "r"(b[1]));
}

// ---------------- kernel 1: fp32 -> bf16 row-major + row norms ----------------
__global__ void __launch_bounds__(128) prep_kernel(const float* __restrict__ x,
                                                   const float* __restrict__ y) {
    const int wid = threadIdx.x >> 5, lid = threadIdx.x & 31;
    const int row = blockIdx.x * 4 + wid;  // 0..16383: x rows then y rows

    const float4* src;
    uint2* dst;
    float* nrm;
    int r;
    if (row < B_ROWS) {
        r = row;
        src = reinterpret_cast<const float4*>(x + (size_t)r * D_DIM);
        dst = reinterpret_cast<uint2*>(g_xb + (size_t)r * D_DIM * 2);
        nrm = g_x2;
    } else {
        r = row - B_ROWS;
        src = reinterpret_cast<const float4*>(y + (size_t)r * D_DIM);
        dst = reinterpret_cast<uint2*>(g_yb + (size_t)r * D_DIM * 2);
        nrm = g_y2;
    }

    float ss = 0.f;
#pragma unroll
    for (int j = 0; j < D_DIM / 128; j++) {  // 6 float4 per lane
        const int idx = j * 32 + lid;
        const float4 v = src[idx];
        ss = fmaf(v.x, v.x, ss);
        ss = fmaf(v.y, v.y, ss);
        ss = fmaf(v.z, v.z, ss);
        ss = fmaf(v.w, v.w, ss);
        __nv_bfloat162 h0 = __floats2bfloat162_rn(v.x, v.y);
        __nv_bfloat162 h1 = __floats2bfloat162_rn(v.z, v.w);
        uint2 o;
        o.x = *reinterpret_cast<uint32_t*>(&h0);
        o.y = *reinterpret_cast<uint32_t*>(&h1);
        dst[idx] = o;
    }
#pragma unroll
    for (int o = 16; o; o >>= 1) ss += __shfl_xor_sync(0xffffffffu, ss, o);
    if (lid == 0) nrm[r] = ss;
}

// ---------------- kernel 2: persistent bf16 mma.sync GEMM + fused epilogue --------
extern __shared__ unsigned char smem[];

__global__ void __launch_bounds__(THREADS, 2) gemm_kernel(float* __restrict__ out) {
    const uint32_t sb = smem_u32(smem);
    const int tid = threadIdx.x;
    const int lid = tid & 31;
    const int wid = tid >> 5;
    const int warpM = wid & 1;   // 0..1
    const int warpN = wid >> 1;  // 0..1

    // ---- per-thread cp.async geometry (constant across tiles) ----
    const int crow = tid >> 3, csc = tid & 7;
    const size_t gthread = (size_t)crow * GROW + csc * 16;  // offset within a tile block
    const uint32_t dAb = sb + crow * ROWB + csc * 16;
    const uint32_t dBb = dAb + STG * TILE;

    // load k-chunk kt of tile with row-bases axb/bxb into stage st
    auto load_stage = [&](int st, const char* axb, const char* bxb, int kt) {
        const uint32_t so = (uint32_t)st * TILE;
        const size_t go = (size_t)kt * (BK * 2);
#pragma unroll
        for (int t = 0; t < 8; t++)
            CP16(dAb + so + t * (16 * ROWB), axb + go + t * (size_t)(16 * GROW));
#pragma unroll
        for (int t = 0; t < 8; t++)
            CP16(dBb + so + t * (16 * ROWB), bxb + go + t * (size_t)(16 * GROW));
    };

    // ---- ldmatrix per-thread offsets (k16 step adds s*32B) ----
    uint32_t aoff[4], boff[4];
#pragma unroll
    for (int t = 0; t < 4; t++)
        aoff[t] = (uint32_t)(warpM * 64 + t * 16 + (lid & 15)) * ROWB + (lid >> 4) * 16;
#pragma unroll
    for (int g = 0; g < 4; g++)
        boff[g] = (uint32_t)(warpN * 64 + g * 16 + (lid & 7) + ((lid >> 4) << 3)) * ROWB +
                  ((lid >> 3) & 1) * 16;

    uint32_t fa[2][4][4], fb[2][4][4];
    auto ldfrags = [&](uint32_t ab, uint32_t bb, int s, int buf) {
#pragma unroll
        for (int t = 0; t < 4; t++) LDSM4(fa[buf][t], ab + aoff[t] + s * 32);
#pragma unroll
        for (int g = 0; g < 4; g++) LDSM4(fb[buf][g], bb + boff[g] + s * 32);
    };

    float acc[4][8][4];
    auto mma_all = [&](int buf) {
#pragma unroll
        for (int tm = 0; tm < 4; tm++)
#pragma unroll
            for (int tn = 0; tn < 8; tn++)
                mma16816(acc[tm][tn], fa[buf][tm], &fb[buf][tn >> 1][(tn & 1) * 2]);
    };

    const int t0 = blockIdx.x;
    if (t0 >= NTILES) return;

    auto abase = [&](int t) {
        return (const char*)g_xb + (size_t)((t / NBN) * BM) * GROW + gthread;
    };
    auto bbase = [&](int t) {
        return (const char*)g_yb + (size_t)((t % NBN) * BN) * GROW + gthread;
    };

    const char* gAc = abase(t0);
    const char* gBc = bbase(t0);

    // ---- prologue (once per CTA): tile t0, k-chunks 0,1 ----
    load_stage(0, gAc, gBc, 0);
    CPCOMMIT();
    load_stage(1, gAc, gBc, 1);
    CPCOMMIT();
    CPWAIT(1);
    __syncthreads();
    ldfrags(sb, sb + STG * TILE, 0, 0);

    // ---- persistent tile loop: pipeline never drains ----
    for (int t = t0; t < NTILES; t += gridDim.x) {
        const int tnx0 = t + gridDim.x;
        const int tnx = (tnx0 < NTILES) ? tnx0 : t;  // clamp: harmless duplicate loads
        const char* gAn = abase(tnx);
        const char* gBn = bbase(tnx);

#pragma unroll
        for (int i = 0; i < 4; i++)
#pragma unroll
            for (int j = 0; j < 8; j++)
#pragma unroll
                for (int k = 0; k < 4; k++) acc[i][j][k] = 0.f;

        for (int i = 0; i < NK; i++) {
            const int st = i % STG;
            const uint32_t ab = sb + (uint32_t)st * TILE;
            const uint32_t bb = ab + STG * TILE;

            ldfrags(ab, bb, 1, 1);
            mma_all(0);

            // load stream chunk i+2: current tile if i+2<NK else next tile's (i+2-NK)
            if (i + 2 < NK) load_stage((i + 2) % STG, gAc, gBc, i + 2);
            else            load_stage((i + 2) % STG, gAn, gBn, i + 2 - NK);
            CPCOMMIT();

            ldfrags(ab, bb, 2, 0);
            mma_all(1);
            ldfrags(ab, bb, 3, 1);
            mma_all(0);

            CPWAIT(1);
            __syncthreads();
            const uint32_t ab2 = sb + (uint32_t)((i + 1) % STG) * TILE;
            ldfrags(ab2, ab2 + STG * TILE, 0, 0);  // overlaps final MMA pack
            mma_all(1);
        }

        // ---- epilogue: registers -> global, no smem, no barriers ----
        const int bm = t / NBN, bn = t % NBN;
        float x2v[4][2], y2v[8][2];
#pragma unroll
        for (int tt = 0; tt < 4; tt++) {
            const int m = bm * BM + warpM * 64 + tt * 16 + (lid >> 2);
            x2v[tt][0] = __ldg(&g_x2[m]);
            x2v[tt][1] = __ldg(&g_x2[m + 8]);
        }
#pragma unroll
        for (int tt = 0; tt < 8; tt++) {
            const int n = bn * BN + warpN * 64 + tt * 8 + 2 * (lid & 3);
            y2v[tt][0] = __ldg(&g_y2[n]);
            y2v[tt][1] = __ldg(&g_y2[n + 1]);
        }

#pragma unroll
        for (int tm = 0; tm < 4; tm++) {
            const int m0 = bm * BM + warpM * 64 + tm * 16 + (lid >> 2);
            float* o0 = out + (size_t)m0 * N_ROWS + bn * BN + warpN * 64 + 2 * (lid & 3);
            float* o1 = o0 + 8 * N_ROWS;
#pragma unroll
            for (int tn = 0; tn < 8; tn++) {
                const float* c = acc[tm][tn];
                float2 lo, hi;
                lo.x = fmaxf(fmaf(-2.f, c[0], x2v[tm][0] + y2v[tn][0]), 0.f);
                lo.y = fmaxf(fmaf(-2.f, c[1], x2v[tm][0] + y2v[tn][1]), 0.f);
                hi.x = fmaxf(fmaf(-2.f, c[2], x2v[tm][1] + y2v[tn][0]), 0.f);
                hi.y = fmaxf(fmaf(-2.f, c[3], x2v[tm][1] + y2v[tn][1]), 0.f);
                *reinterpret_cast<float2*>(o0 + tn * 8) = lo;
                *reinterpret_cast<float2*>(o1 + tn * 8) = hi;
            }
        }

        gAc = gAn;
        gBc = gBn;
    }
}

// ---------------- launch ----------------
extern "C" void kernel_launch(void* const* d_in, const int* in_sizes, int n_in,
                              void* d_out, int out_size) {
    (void)in_sizes; (void)n_in; (void)out_size;
    const float* x = (const float*)d_in[0];
    const float* y = (const float*)d_in[1];
    float* out = (float*)d_out;

    cudaFuncSetAttribute(gemm_kernel, cudaFuncAttributeMaxDynamicSharedMemorySize,
                         (int)SMEM_TOTAL);

    int dev = 0, nsm = 148;
    cudaGetDevice(&dev);
    cudaDeviceGetAttribute(&nsm, cudaDevAttrMultiProcessorCount, dev);
    int grid = 2 * nsm;
    if (grid > NTILES) grid = NTILES;

    prep_kernel<<<(B_ROWS + N_ROWS) / 4, 128>>>(x, y);
    gemm_kernel<<<grid, THREADS, SMEM_TOTAL>>>(out);
}